// round 7
// baseline (speedup 1.0000x reference)
#include <cuda_runtime.h>

// Problem shape (fixed by setup_inputs): x (B=1024, S=1024, E=12), n_qubits = 12.
#define BB    1024
#define SSZ   1024
#define EE    12
#define EPSV  1e-5f
#define CHUNK 128    // s-rows per block in k2
#define BPB   8      // b-values per block in k2
#define NBUF  4      // cp.async buffers (6 KB each)

// Scratch tables: attn[s][e], ffn[s][e]  (s in 0..1023, e in 0..11)
__device__ float g_attn[BB * EE];
__device__ float g_ffn [BB * EE];

// ---------------------------------------------------------------------------
// Kernel 1: per-row quantum "attention" and "ffn" tables (analytic collapse).
// One warp per j; 128 blocks x 256 threads.
// ---------------------------------------------------------------------------
__global__ __launch_bounds__(256) void qtb_k1(
    const float* __restrict__ x,
    const float* __restrict__ rxa,
    const float* __restrict__ rya,
    const float* __restrict__ wffn,   // (E, 12) row-major
    const float* __restrict__ bffn,
    const float* __restrict__ g1,
    const float* __restrict__ b1)
{
    __shared__ float s_attn12[12][12];            // attn rows 0..11 (for tok2)
    __shared__ __align__(16) float swx[8][148];   // per-warp x[j,0:12,0:12]
    __shared__ float scrx[12];

    const int tid  = threadIdx.x;
    const int warp = tid >> 5;
    const int lane = tid & 31;
    const int j    = blockIdx.x * 8 + warp;       // 0..1023

    if (tid < 12) scrx[tid] = __cosf(__ldg(&rxa[tid]));

    // Stage this warp's 144 contiguous floats (36 float4, coalesced)
    {
        const float4* xr = reinterpret_cast<const float4*>(x + (size_t)j * SSZ * EE);
        float4* sw = reinterpret_cast<float4*>(&swx[warp][0]);
        for (int t = lane; t < 36; t += 32) sw[t] = xr[t];
    }

    // Phase A0: attn rows 0..11 into smem (144 of 256 threads)
    if (tid < 144) {
        const int i = tid / 12;
        const int w = tid % 12;
        float z[12];
        #pragma unroll
        for (int k = 0; k < 12; k++)
            z[k] = __cosf(__ldg(&rxa[k])) * __cosf(__ldg(&x[(size_t)i * SSZ * EE + k * EE]));
        float p = 1.0f;
        if (w == 0) {
            #pragma unroll
            for (int k = 1; k < 12; k++) p *= z[k];
        } else {
            for (int k = 0; k <= w; k++) p *= z[k];
        }
        s_attn12[i][w] = p;
    }
    __syncthreads();

    // Phase A: this warp's own attn row (lane i holds z_i, shuffle products)
    float zl = 0.0f;
    if (lane < 12)
        zl = scrx[lane] * __cosf(swx[warp][lane * 12]);
    float aw = 1.0f;
    #pragma unroll
    for (int k = 0; k < 12; k++) {
        float zk = __shfl_sync(0xffffffffu, zl, k);
        bool incl = (lane == 0) ? (k >= 1) : (k <= lane);
        if (incl) aw *= zk;
    }
    if (lane < 12) g_attn[j * 12 + lane] = aw;

    // Phase B: lane i<12 computes tok2_i via the 12-wide LN of row (j,i)
    float r = 0.0f;
    if (lane < 12) {
        float v[12];
        float mu = 0.0f;
        #pragma unroll
        for (int e = 0; e < 12; e++) {
            v[e] = swx[warp][lane * 12 + e] + s_attn12[lane][e];
            mu  += v[e];
        }
        mu *= (1.0f / 12.0f);
        float var = 0.0f;
        #pragma unroll
        for (int e = 0; e < 12; e++) { float d = v[e] - mu; var += d * d; }
        var *= (1.0f / 12.0f);
        const float inv  = rsqrtf(var + EPSV);
        const float tok2 = (v[0] - mu) * inv * __ldg(&g1[0]) + __ldg(&b1[0]);
        r = fmaxf(__cosf(tok2 + __ldg(&rya[lane])), 0.0f);
    }

    // Phase C: ffn[j,e] = b_ffn[e] + sum_i r_i * w_ffn[e,i]
    float acc = (lane < 12) ? __ldg(&bffn[lane]) : 0.0f;
    #pragma unroll
    for (int i = 0; i < 12; i++) {
        float ri = __shfl_sync(0xffffffffu, r, i);
        if (lane < 12) acc = fmaf(ri, __ldg(&wffn[lane * 12 + i]), acc);
    }
    if (lane < 12) g_ffn[j * 12 + lane] = acc;
}

// ---------------------------------------------------------------------------
// Double-LN for one row, given v[12] = x-row + attn (in place), params in smem,
// ffn in regs. Produces three output float4s.
// ---------------------------------------------------------------------------
__device__ __forceinline__ void double_ln(
    float v[12], const float fn[12],
    const float* sG1, const float* sB1,
    const float* sG2, const float* sB2,
    float4& o0, float4& o1, float4& o2)
{
    float mu = 0.0f;
    #pragma unroll
    for (int e = 0; e < 12; e++) mu += v[e];
    mu *= (1.0f / 12.0f);
    float var = 0.0f;
    #pragma unroll
    for (int e = 0; e < 12; e++) { float d = v[e] - mu; var += d * d; }
    var *= (1.0f / 12.0f);
    const float inv = rsqrtf(var + EPSV);

    float u[12];
    float mu2 = 0.0f;
    #pragma unroll
    for (int e = 0; e < 12; e++) {
        u[e] = (v[e] - mu) * inv * sG1[e] + sB1[e] + fn[e];
        mu2 += u[e];
    }
    mu2 *= (1.0f / 12.0f);
    float var2 = 0.0f;
    #pragma unroll
    for (int e = 0; e < 12; e++) { float d = u[e] - mu2; var2 += d * d; }
    var2 *= (1.0f / 12.0f);
    const float inv2 = rsqrtf(var2 + EPSV);

    o0.x = (u[0]  - mu2) * inv2 * sG2[0]  + sB2[0];
    o0.y = (u[1]  - mu2) * inv2 * sG2[1]  + sB2[1];
    o0.z = (u[2]  - mu2) * inv2 * sG2[2]  + sB2[2];
    o0.w = (u[3]  - mu2) * inv2 * sG2[3]  + sB2[3];
    o1.x = (u[4]  - mu2) * inv2 * sG2[4]  + sB2[4];
    o1.y = (u[5]  - mu2) * inv2 * sG2[5]  + sB2[5];
    o1.z = (u[6]  - mu2) * inv2 * sG2[6]  + sB2[6];
    o1.w = (u[7]  - mu2) * inv2 * sG2[7]  + sB2[7];
    o2.x = (u[8]  - mu2) * inv2 * sG2[8]  + sB2[8];
    o2.y = (u[9]  - mu2) * inv2 * sG2[9]  + sB2[9];
    o2.z = (u[10] - mu2) * inv2 * sG2[10] + sB2[10];
    o2.w = (u[11] - mu2) * inv2 * sG2[11] + sB2[11];
}

// ---------------------------------------------------------------------------
// Kernel 2: out[b,s,:] = LN2( LN1(x[b,s,:] + attn[s,:]) + ffn[s,:] )
// Block-wide cp.async pipeline, 4 buffers; each iteration processes TWO
// b-values (two independent LN chains per thread -> 2x ILP). Output via
// direct strided STG.cs. grid (SSZ/CHUNK, BB/BPB), 128 threads.
// ---------------------------------------------------------------------------
__global__ __launch_bounds__(128) void qtb_k2(
    const float* __restrict__ x,
    const float* __restrict__ g1, const float* __restrict__ b1,
    const float* __restrict__ g2, const float* __restrict__ b2,
    float* __restrict__ out)
{
    __shared__ __align__(16) float sx[NBUF][CHUNK * 12];   // 24 KB
    __shared__ float sG1[12], sB1[12], sG2[12], sB2[12];

    const int tid   = threadIdx.x;
    const int sbase = blockIdx.x * CHUNK;
    const int b0    = blockIdx.y * BPB;
    const int s     = sbase + tid;

    const float* xbase = x   + ((size_t)b0 * SSZ + sbase) * EE;
    float*       obase = out + ((size_t)b0 * SSZ + s) * EE;   // this thread's row
    const size_t bstride = (size_t)SSZ * EE;

    // cp.async stage of one 6 KB x-chunk into buffer `buf`
    auto issue_load = [&](int buf, int bi) {
        const float* src = xbase + (size_t)bi * bstride;
        unsigned dst = (unsigned)__cvta_generic_to_shared(&sx[buf][0]);
        #pragma unroll
        for (int k = 0; k < 3; k++) {
            asm volatile("cp.async.cg.shared.global [%0], [%1], 16;\n"
                         :: "r"(dst + (tid + 128 * k) * 16),
                            "l"(src + (tid + 128 * k) * 4));
        }
        asm volatile("cp.async.commit_group;\n");
    };

    // Fill the pipeline first so prologue L2 loads overlap with it
    issue_load(0, 0); issue_load(1, 1); issue_load(2, 2); issue_load(3, 3);

    if (tid < 12) {
        sG1[tid] = g1[tid]; sB1[tid] = b1[tid];
        sG2[tid] = g2[tid]; sB2[tid] = b2[tid];
    }

    // attn/ffn for this thread's row -> registers (g_* tables are L2-hot)
    float an[12], fn[12];
    {
        const float4* ap = reinterpret_cast<const float4*>(&g_attn[s * 12]);
        const float4* fp = reinterpret_cast<const float4*>(&g_ffn [s * 12]);
        float4 a0 = ap[0], a1 = ap[1], a2 = ap[2];
        float4 f0 = fp[0], f1 = fp[1], f2 = fp[2];
        an[0]=a0.x; an[1]=a0.y; an[2]=a0.z; an[3]=a0.w;
        an[4]=a1.x; an[5]=a1.y; an[6]=a1.z; an[7]=a1.w;
        an[8]=a2.x; an[9]=a2.y; an[10]=a2.z; an[11]=a2.w;
        fn[0]=f0.x; fn[1]=f0.y; fn[2]=f0.z; fn[3]=f0.w;
        fn[4]=f1.x; fn[5]=f1.y; fn[6]=f1.z; fn[7]=f1.w;
        fn[8]=f2.x; fn[9]=f2.y; fn[10]=f2.z; fn[11]=f2.w;
    }

    #pragma unroll
    for (int p = 0; p < BPB / 2; p++) {
        const int bi0  = 2 * p;
        const int buf0 = bi0 & (NBUF - 1);
        const int buf1 = (bi0 + 1) & (NBUF - 1);

        if (p < BPB / 2 - 1) asm volatile("cp.async.wait_group 2;\n");
        else                 asm volatile("cp.async.wait_group 0;\n");
        __syncthreads();   // buffers buf0,buf1 visible to all (+ sG/sB on p==0)

        // Two independent rows -> 2x ILP. LDS.128 at 48B stride: conflict-free.
        const float4* rA = reinterpret_cast<const float4*>(&sx[buf0][tid * 12]);
        const float4* rB = reinterpret_cast<const float4*>(&sx[buf1][tid * 12]);
        float4 qa0 = rA[0], qa1 = rA[1], qa2 = rA[2];
        float4 qb0 = rB[0], qb1 = rB[1], qb2 = rB[2];

        float vA[12], vB[12];
        vA[0]=qa0.x+an[0]; vA[1]=qa0.y+an[1]; vA[2]=qa0.z+an[2]; vA[3]=qa0.w+an[3];
        vA[4]=qa1.x+an[4]; vA[5]=qa1.y+an[5]; vA[6]=qa1.z+an[6]; vA[7]=qa1.w+an[7];
        vA[8]=qa2.x+an[8]; vA[9]=qa2.y+an[9]; vA[10]=qa2.z+an[10]; vA[11]=qa2.w+an[11];
        vB[0]=qb0.x+an[0]; vB[1]=qb0.y+an[1]; vB[2]=qb0.z+an[2]; vB[3]=qb0.w+an[3];
        vB[4]=qb1.x+an[4]; vB[5]=qb1.y+an[5]; vB[6]=qb1.z+an[6]; vB[7]=qb1.w+an[7];
        vB[8]=qb2.x+an[8]; vB[9]=qb2.y+an[9]; vB[10]=qb2.z+an[10]; vB[11]=qb2.w+an[11];

        float4 a0, a1, a2, c0, c1, c2;
        double_ln(vA, fn, sG1, sB1, sG2, sB2, a0, a1, a2);
        double_ln(vB, fn, sG1, sB1, sG2, sB2, c0, c1, c2);

        float4* opA = reinterpret_cast<float4*>(obase + (size_t)bi0 * bstride);
        float4* opB = reinterpret_cast<float4*>(obase + (size_t)(bi0 + 1) * bstride);
        __stcs(&opA[0], a0); __stcs(&opA[1], a1); __stcs(&opA[2], a2);
        __stcs(&opB[0], c0); __stcs(&opB[1], c1); __stcs(&opB[2], c2);

        __syncthreads();   // everyone done reading buf0/buf1 before refill
        if (bi0 + 5 < BPB) {
            issue_load(buf0, bi0 + 4);
            issue_load(buf1, bi0 + 5);
        }
    }
}

// ---------------------------------------------------------------------------
extern "C" void kernel_launch(void* const* d_in, const int* in_sizes, int n_in,
                              void* d_out, int out_size)
{
    const float* x    = (const float*)d_in[0];   // (1024, 1024, 12)
    const float* rxa  = (const float*)d_in[1];   // (12,)
    const float* rya  = (const float*)d_in[2];   // (12,)
    const float* wffn = (const float*)d_in[3];   // (12, 12)
    const float* bffn = (const float*)d_in[4];   // (12,)
    const float* g1   = (const float*)d_in[5];
    const float* b1   = (const float*)d_in[6];
    const float* g2   = (const float*)d_in[7];
    const float* b2   = (const float*)d_in[8];
    float* out = (float*)d_out;

    qtb_k1<<<BB / 8, 256>>>(x, rxa, rya, wffn, bffn, g1, b1);
    qtb_k2<<<dim3(SSZ / CHUNK, BB / BPB), 128>>>(x, g1, b1, g2, b2, out);
}

// round 9
// speedup vs baseline: 1.0884x; 1.0884x over previous
#include <cuda_runtime.h>

// Problem shape (fixed by setup_inputs): x (B=1024, S=1024, E=12), n_qubits = 12.
#define BB    1024
#define SSZ   1024
#define EE    12
#define EPSV  1e-5f
#define CHUNK 128    // s-rows per block in k2
#define BPB   4      // b-values per block in k2  (8 -> 4: 2x warp concurrency)
#define NSTG  3      // cp.async pipeline depth

// Scratch tables: attn[s][e], ffn[s][e]  (s in 0..1023, e in 0..11)
__device__ float g_attn[BB * EE];
__device__ float g_ffn [BB * EE];

// ---------------------------------------------------------------------------
// Kernel 1: per-row quantum "attention" and "ffn" tables (analytic collapse).
// One warp per j; 128 blocks x 256 threads.
// ---------------------------------------------------------------------------
__global__ __launch_bounds__(256) void qtb_k1(
    const float* __restrict__ x,
    const float* __restrict__ rxa,
    const float* __restrict__ rya,
    const float* __restrict__ wffn,   // (E, 12) row-major
    const float* __restrict__ bffn,
    const float* __restrict__ g1,
    const float* __restrict__ b1)
{
    __shared__ float s_attn12[12][12];            // attn rows 0..11 (for tok2)
    __shared__ __align__(16) float swx[8][148];   // per-warp x[j,0:12,0:12]
    __shared__ float scrx[12];

    const int tid  = threadIdx.x;
    const int warp = tid >> 5;
    const int lane = tid & 31;
    const int j    = blockIdx.x * 8 + warp;       // 0..1023

    if (tid < 12) scrx[tid] = __cosf(__ldg(&rxa[tid]));

    // Stage this warp's 144 contiguous floats (36 float4, coalesced)
    {
        const float4* xr = reinterpret_cast<const float4*>(x + (size_t)j * SSZ * EE);
        float4* sw = reinterpret_cast<float4*>(&swx[warp][0]);
        for (int t = lane; t < 36; t += 32) sw[t] = xr[t];
    }

    // Phase A0: attn rows 0..11 into smem (144 of 256 threads)
    if (tid < 144) {
        const int i = tid / 12;
        const int w = tid % 12;
        float z[12];
        #pragma unroll
        for (int k = 0; k < 12; k++)
            z[k] = __cosf(__ldg(&rxa[k])) * __cosf(__ldg(&x[(size_t)i * SSZ * EE + k * EE]));
        float p = 1.0f;
        if (w == 0) {
            #pragma unroll
            for (int k = 1; k < 12; k++) p *= z[k];
        } else {
            for (int k = 0; k <= w; k++) p *= z[k];
        }
        s_attn12[i][w] = p;
    }
    __syncthreads();

    // Phase A: this warp's own attn row (lane i holds z_i, shuffle products)
    float zl = 0.0f;
    if (lane < 12)
        zl = scrx[lane] * __cosf(swx[warp][lane * 12]);
    float aw = 1.0f;
    #pragma unroll
    for (int k = 0; k < 12; k++) {
        float zk = __shfl_sync(0xffffffffu, zl, k);
        bool incl = (lane == 0) ? (k >= 1) : (k <= lane);
        if (incl) aw *= zk;
    }
    if (lane < 12) g_attn[j * 12 + lane] = aw;

    // Phase B: lane i<12 computes tok2_i via the 12-wide LN of row (j,i)
    float r = 0.0f;
    if (lane < 12) {
        float v[12];
        float mu = 0.0f;
        #pragma unroll
        for (int e = 0; e < 12; e++) {
            v[e] = swx[warp][lane * 12 + e] + s_attn12[lane][e];
            mu  += v[e];
        }
        mu *= (1.0f / 12.0f);
        float var = 0.0f;
        #pragma unroll
        for (int e = 0; e < 12; e++) { float d = v[e] - mu; var += d * d; }
        var *= (1.0f / 12.0f);
        const float inv  = rsqrtf(var + EPSV);
        const float tok2 = (v[0] - mu) * inv * __ldg(&g1[0]) + __ldg(&b1[0]);
        r = fmaxf(__cosf(tok2 + __ldg(&rya[lane])), 0.0f);
    }

    // Phase C: ffn[j,e] = b_ffn[e] + sum_i r_i * w_ffn[e,i]
    float acc = (lane < 12) ? __ldg(&bffn[lane]) : 0.0f;
    #pragma unroll
    for (int i = 0; i < 12; i++) {
        float ri = __shfl_sync(0xffffffffu, r, i);
        if (lane < 12) acc = fmaf(ri, __ldg(&wffn[lane * 12 + i]), acc);
    }
    if (lane < 12) g_ffn[j * 12 + lane] = acc;
}

// ---------------------------------------------------------------------------
// Kernel 2: out[b,s,:] = LN2( LN1(x[b,s,:] + attn[s,:]) + ffn[s,:] )
// R5 structure: block-wide 3-stage cp.async pipeline for x; attn/ffn
// register-resident; direct strided STG.cs output. BPB=4 -> 2048 blocks
// (8192 warps) to lift the grid-capped occupancy.
// grid (SSZ/CHUNK, BB/BPB), 128 threads.
// ---------------------------------------------------------------------------
__global__ __launch_bounds__(128) void qtb_k2(
    const float* __restrict__ x,
    const float* __restrict__ g1, const float* __restrict__ b1,
    const float* __restrict__ g2, const float* __restrict__ b2,
    float* __restrict__ out)
{
    __shared__ __align__(16) float sx[NSTG][CHUNK * 12];   // 18 KB
    __shared__ float sG1[12], sB1[12], sG2[12], sB2[12];

    const int tid   = threadIdx.x;
    const int sbase = blockIdx.x * CHUNK;
    const int b0    = blockIdx.y * BPB;
    const int s     = sbase + tid;

    const float* xbase = x   + ((size_t)b0 * SSZ + sbase) * EE;
    float*       obase = out + ((size_t)b0 * SSZ + s) * EE;   // this thread's row
    const size_t bstride = (size_t)SSZ * EE;

    // cp.async stage of one 6 KB x-chunk into pipeline stage `buf`
    auto issue_load = [&](int buf, int bi) {
        const float* src = xbase + (size_t)bi * bstride;
        unsigned dst = (unsigned)__cvta_generic_to_shared(&sx[buf][0]);
        #pragma unroll
        for (int k = 0; k < 3; k++) {
            asm volatile("cp.async.cg.shared.global [%0], [%1], 16;\n"
                         :: "r"(dst + (tid + 128 * k) * 16),
                            "l"(src + (tid + 128 * k) * 4));
        }
        asm volatile("cp.async.commit_group;\n");
    };

    // Fill pipeline first so prologue L2 loads overlap with it
    issue_load(0, 0);
    issue_load(1, 1);

    if (tid < 12) {
        sG1[tid] = g1[tid]; sB1[tid] = b1[tid];
        sG2[tid] = g2[tid]; sB2[tid] = b2[tid];
    }

    // attn/ffn for this thread's row -> registers (g_* tables are L2-hot)
    float an[12], fn[12];
    {
        const float4* ap = reinterpret_cast<const float4*>(&g_attn[s * 12]);
        const float4* fp = reinterpret_cast<const float4*>(&g_ffn [s * 12]);
        float4 a0 = ap[0], a1 = ap[1], a2 = ap[2];
        float4 f0 = fp[0], f1 = fp[1], f2 = fp[2];
        an[0]=a0.x; an[1]=a0.y; an[2]=a0.z; an[3]=a0.w;
        an[4]=a1.x; an[5]=a1.y; an[6]=a1.z; an[7]=a1.w;
        an[8]=a2.x; an[9]=a2.y; an[10]=a2.z; an[11]=a2.w;
        fn[0]=f0.x; fn[1]=f0.y; fn[2]=f0.z; fn[3]=f0.w;
        fn[4]=f1.x; fn[5]=f1.y; fn[6]=f1.z; fn[7]=f1.w;
        fn[8]=f2.x; fn[9]=f2.y; fn[10]=f2.z; fn[11]=f2.w;
    }

    #pragma unroll
    for (int bi = 0; bi < BPB; bi++) {
        if (bi + 1 < BPB) asm volatile("cp.async.wait_group 1;\n");  // group bi done
        else              asm volatile("cp.async.wait_group 0;\n");
        __syncthreads();   // buffer bi%NSTG ready for all; all threads past iter bi-1
        if (bi + 2 < BPB) issue_load((bi + 2) % NSTG, bi + 2);
        // (overwrites buffer last read at iter bi-1 -> safe after the sync above)

        const int cur = bi % NSTG;
        // Thread owns row tid. LDS.128 at 48B stride: conflict-free.
        const float4* row = reinterpret_cast<const float4*>(&sx[cur][tid * 12]);
        float4 q0 = row[0], q1 = row[1], q2 = row[2];

        float v[12];
        v[0]=q0.x; v[1]=q0.y; v[2]=q0.z; v[3]=q0.w;
        v[4]=q1.x; v[5]=q1.y; v[6]=q1.z; v[7]=q1.w;
        v[8]=q2.x; v[9]=q2.y; v[10]=q2.z; v[11]=q2.w;

        // x + attn, LN1
        float mu = 0.0f;
        #pragma unroll
        for (int e = 0; e < 12; e++) { v[e] += an[e]; mu += v[e]; }
        mu *= (1.0f / 12.0f);
        float var = 0.0f;
        #pragma unroll
        for (int e = 0; e < 12; e++) { float d = v[e] - mu; var += d * d; }
        var *= (1.0f / 12.0f);
        const float inv = rsqrtf(var + EPSV);

        // x1 + ffn, LN2
        float u[12];
        float mu2 = 0.0f;
        #pragma unroll
        for (int e = 0; e < 12; e++) {
            u[e] = (v[e] - mu) * inv * sG1[e] + sB1[e] + fn[e];
            mu2 += u[e];
        }
        mu2 *= (1.0f / 12.0f);
        float var2 = 0.0f;
        #pragma unroll
        for (int e = 0; e < 12; e++) { float d = u[e] - mu2; var2 += d * d; }
        var2 *= (1.0f / 12.0f);
        const float inv2 = rsqrtf(var2 + EPSV);

        float4 o0, o1, o2;
        o0.x = (u[0]  - mu2) * inv2 * sG2[0]  + sB2[0];
        o0.y = (u[1]  - mu2) * inv2 * sG2[1]  + sB2[1];
        o0.z = (u[2]  - mu2) * inv2 * sG2[2]  + sB2[2];
        o0.w = (u[3]  - mu2) * inv2 * sG2[3]  + sB2[3];
        o1.x = (u[4]  - mu2) * inv2 * sG2[4]  + sB2[4];
        o1.y = (u[5]  - mu2) * inv2 * sG2[5]  + sB2[5];
        o1.z = (u[6]  - mu2) * inv2 * sG2[6]  + sB2[6];
        o1.w = (u[7]  - mu2) * inv2 * sG2[7]  + sB2[7];
        o2.x = (u[8]  - mu2) * inv2 * sG2[8]  + sB2[8];
        o2.y = (u[9]  - mu2) * inv2 * sG2[9]  + sB2[9];
        o2.z = (u[10] - mu2) * inv2 * sG2[10] + sB2[10];
        o2.w = (u[11] - mu2) * inv2 * sG2[11] + sB2[11];

        // Streaming stores: 48B/thread, warp covers 1536B contiguous (full lines)
        float4* op = reinterpret_cast<float4*>(obase + (size_t)bi * bstride);
        __stcs(&op[0], o0);
        __stcs(&op[1], o1);
        __stcs(&op[2], o2);
    }
}

// ---------------------------------------------------------------------------
extern "C" void kernel_launch(void* const* d_in, const int* in_sizes, int n_in,
                              void* d_out, int out_size)
{
    const float* x    = (const float*)d_in[0];   // (1024, 1024, 12)
    const float* rxa  = (const float*)d_in[1];   // (12,)
    const float* rya  = (const float*)d_in[2];   // (12,)
    const float* wffn = (const float*)d_in[3];   // (12, 12)
    const float* bffn = (const float*)d_in[4];   // (12,)
    const float* g1   = (const float*)d_in[5];
    const float* b1   = (const float*)d_in[6];
    const float* g2   = (const float*)d_in[7];
    const float* b2   = (const float*)d_in[8];
    float* out = (float*)d_out;

    qtb_k1<<<BB / 8, 256>>>(x, rxa, rya, wffn, bffn, g1, b1);
    qtb_k2<<<dim3(SSZ / CHUNK, BB / BPB), 128>>>(x, g1, b1, g2, b2, out);
}

// round 10
// speedup vs baseline: 1.1657x; 1.0710x over previous
#include <cuda_runtime.h>

// Problem shape (fixed by setup_inputs): x (B=1024, S=1024, E=12), n_qubits = 12.
#define BB    1024
#define SSZ   1024
#define EE    12
#define EPSV  1e-5f
#define ROWS_PER_WARP 10   // 3 lanes per row, lanes 30-31 idle
#define SROWS  40          // rows per 128-thread block (4 warps)
#define NBY    64          // b-tiles
#define NB     (BB / NBY)  // 16 b per block

// Scratch tables: attn[s][e], ffn[s][e]  (s in 0..1023, e in 0..11)
__device__ float g_attn[BB * EE];
__device__ float g_ffn [BB * EE];

// ---------------------------------------------------------------------------
// Kernel 1: per-row quantum "attention" and "ffn" tables (analytic collapse).
// One warp per j; 128 blocks x 256 threads.
// ---------------------------------------------------------------------------
__global__ __launch_bounds__(256) void qtb_k1(
    const float* __restrict__ x,
    const float* __restrict__ rxa,
    const float* __restrict__ rya,
    const float* __restrict__ wffn,   // (E, 12) row-major
    const float* __restrict__ bffn,
    const float* __restrict__ g1,
    const float* __restrict__ b1)
{
    __shared__ float s_attn12[12][12];            // attn rows 0..11 (for tok2)
    __shared__ __align__(16) float swx[8][148];   // per-warp x[j,0:12,0:12]
    __shared__ float scrx[12];

    const int tid  = threadIdx.x;
    const int warp = tid >> 5;
    const int lane = tid & 31;
    const int j    = blockIdx.x * 8 + warp;       // 0..1023

    if (tid < 12) scrx[tid] = __cosf(__ldg(&rxa[tid]));

    // Stage this warp's 144 contiguous floats (36 float4, coalesced)
    {
        const float4* xr = reinterpret_cast<const float4*>(x + (size_t)j * SSZ * EE);
        float4* sw = reinterpret_cast<float4*>(&swx[warp][0]);
        for (int t = lane; t < 36; t += 32) sw[t] = xr[t];
    }

    // Phase A0: attn rows 0..11 into smem (144 of 256 threads)
    if (tid < 144) {
        const int i = tid / 12;
        const int w = tid % 12;
        float z[12];
        #pragma unroll
        for (int k = 0; k < 12; k++)
            z[k] = __cosf(__ldg(&rxa[k])) * __cosf(__ldg(&x[(size_t)i * SSZ * EE + k * EE]));
        float p = 1.0f;
        if (w == 0) {
            #pragma unroll
            for (int k = 1; k < 12; k++) p *= z[k];
        } else {
            for (int k = 0; k <= w; k++) p *= z[k];
        }
        s_attn12[i][w] = p;
    }
    __syncthreads();

    // Phase A: this warp's own attn row (lane i holds z_i, shuffle products)
    float zl = 0.0f;
    if (lane < 12)
        zl = scrx[lane] * __cosf(swx[warp][lane * 12]);
    float aw = 1.0f;
    #pragma unroll
    for (int k = 0; k < 12; k++) {
        float zk = __shfl_sync(0xffffffffu, zl, k);
        bool incl = (lane == 0) ? (k >= 1) : (k <= lane);
        if (incl) aw *= zk;
    }
    if (lane < 12) g_attn[j * 12 + lane] = aw;

    // Phase B: lane i<12 computes tok2_i via the 12-wide LN of row (j,i)
    float r = 0.0f;
    if (lane < 12) {
        float v[12];
        float mu = 0.0f;
        #pragma unroll
        for (int e = 0; e < 12; e++) {
            v[e] = swx[warp][lane * 12 + e] + s_attn12[lane][e];
            mu  += v[e];
        }
        mu *= (1.0f / 12.0f);
        float var = 0.0f;
        #pragma unroll
        for (int e = 0; e < 12; e++) { float d = v[e] - mu; var += d * d; }
        var *= (1.0f / 12.0f);
        const float inv  = rsqrtf(var + EPSV);
        const float tok2 = (v[0] - mu) * inv * __ldg(&g1[0]) + __ldg(&b1[0]);
        r = fmaxf(__cosf(tok2 + __ldg(&rya[lane])), 0.0f);
    }

    // Phase C: ffn[j,e] = b_ffn[e] + sum_i r_i * w_ffn[e,i]
    float acc = (lane < 12) ? __ldg(&bffn[lane]) : 0.0f;
    #pragma unroll
    for (int i = 0; i < 12; i++) {
        float ri = __shfl_sync(0xffffffffu, r, i);
        if (lane < 12) acc = fmaf(ri, __ldg(&wffn[lane * 12 + i]), acc);
    }
    if (lane < 12) g_ffn[j * 12 + lane] = acc;
}

// ---------------------------------------------------------------------------
// Kernel 2: out[b,s,:] = LN2( LN1(x[b,s,:] + attn[s,:]) + ffn[s,:] )
// 3-LANES-PER-ROW mapping: lane owns elements e0..e0+3 (e0=(lane%3)*4) of row
// s0+lane/3. Per-warp global addresses = base + 16*lane -> every LDG.128 /
// STG.128 perfectly contiguous. Row reductions via 3-source shuffles.
// NO shared memory, NO barriers: pure dataflow across independent b-iters.
// grid (ceil(SSZ/SROWS), NBY), 128 threads.
// ---------------------------------------------------------------------------
__global__ __launch_bounds__(128) void qtb_k2(
    const float* __restrict__ x,
    const float* __restrict__ g1, const float* __restrict__ b1,
    const float* __restrict__ g2, const float* __restrict__ b2,
    float* __restrict__ out)
{
    const int tid  = threadIdx.x;
    const int warp = tid >> 5;
    const int lane = tid & 31;

    const int grp  = lane / 3;                  // 0..9 (10 for lanes 30,31)
    const int g0   = grp * 3;                   // first lane of group
    const int sloc = blockIdx.x * SROWS + warp * ROWS_PER_WARP + grp;
    const bool valid = (lane < 30) && (sloc < SSZ);
    const int srow = valid ? sloc : (SSZ - 1);  // clamp for safe loads
    const int e0   = (lane - g0) * 4;           // 0, 4, or 8

    // Per-lane slices (registers): attn, ffn, LN params at [srow, e0..e0+3]
    const float4 an = *reinterpret_cast<const float4*>(&g_attn[srow * 12 + e0]);
    const float4 fn = *reinterpret_cast<const float4*>(&g_ffn [srow * 12 + e0]);
    const float4 w1 = __ldg(reinterpret_cast<const float4*>(g1 + e0));
    const float4 c1 = __ldg(reinterpret_cast<const float4*>(b1 + e0));
    const float4 w2 = __ldg(reinterpret_cast<const float4*>(g2 + e0));
    const float4 c2 = __ldg(reinterpret_cast<const float4*>(b2 + e0));

    const int b0 = blockIdx.y * NB;
    // Lane address: (b*SSZ + srow)*12 + e0 = (b*SSZ)*12 + s0*12 + 4*lane
    const size_t base0 = ((size_t)b0 * SSZ + srow) * EE + e0;
    const size_t bstride = (size_t)SSZ * EE;

    const unsigned FULL = 0xffffffffu;

    #pragma unroll 4
    for (int bi = 0; bi < NB; bi++) {
        const float4 q = __ldg(reinterpret_cast<const float4*>(x + base0 + bi * bstride));

        // v = x + attn
        float vx = q.x + an.x, vy = q.y + an.y, vz = q.z + an.z, vw = q.w + an.w;

        // mu1 = mean over 12 (3-lane reduce)
        float ps = (vx + vy) + (vz + vw);
        float tot = __shfl_sync(FULL, ps, g0) + __shfl_sync(FULL, ps, g0 + 1)
                  + __shfl_sync(FULL, ps, g0 + 2);
        const float mu = tot * (1.0f / 12.0f);

        // var1
        float dx = vx - mu, dy = vy - mu, dz = vz - mu, dw = vw - mu;
        float ps2 = (dx * dx + dy * dy) + (dz * dz + dw * dw);
        float tot2 = __shfl_sync(FULL, ps2, g0) + __shfl_sync(FULL, ps2, g0 + 1)
                   + __shfl_sync(FULL, ps2, g0 + 2);
        const float inv = rsqrtf(tot2 * (1.0f / 12.0f) + EPSV);

        // u = LN1 * g1 + b1 + ffn
        float ux = dx * inv * w1.x + c1.x + fn.x;
        float uy = dy * inv * w1.y + c1.y + fn.y;
        float uz = dz * inv * w1.z + c1.z + fn.z;
        float uw = dw * inv * w1.w + c1.w + fn.w;

        // mu2
        float ps3 = (ux + uy) + (uz + uw);
        float tot3 = __shfl_sync(FULL, ps3, g0) + __shfl_sync(FULL, ps3, g0 + 1)
                   + __shfl_sync(FULL, ps3, g0 + 2);
        const float mu2 = tot3 * (1.0f / 12.0f);

        // var2
        float ex = ux - mu2, ey = uy - mu2, ez = uz - mu2, ew = uw - mu2;
        float ps4 = (ex * ex + ey * ey) + (ez * ez + ew * ew);
        float tot4 = __shfl_sync(FULL, ps4, g0) + __shfl_sync(FULL, ps4, g0 + 1)
                   + __shfl_sync(FULL, ps4, g0 + 2);
        const float inv2 = rsqrtf(tot4 * (1.0f / 12.0f) + EPSV);

        float4 o;
        o.x = ex * inv2 * w2.x + c2.x;
        o.y = ey * inv2 * w2.y + c2.y;
        o.z = ez * inv2 * w2.z + c2.z;
        o.w = ew * inv2 * w2.w + c2.w;

        if (valid)
            __stcs(reinterpret_cast<float4*>(out + base0 + bi * bstride), o);
    }
}

// ---------------------------------------------------------------------------
extern "C" void kernel_launch(void* const* d_in, const int* in_sizes, int n_in,
                              void* d_out, int out_size)
{
    const float* x    = (const float*)d_in[0];   // (1024, 1024, 12)
    const float* rxa  = (const float*)d_in[1];   // (12,)
    const float* rya  = (const float*)d_in[2];   // (12,)
    const float* wffn = (const float*)d_in[3];   // (12, 12)
    const float* bffn = (const float*)d_in[4];   // (12,)
    const float* g1   = (const float*)d_in[5];
    const float* b1   = (const float*)d_in[6];
    const float* g2   = (const float*)d_in[7];
    const float* b2   = (const float*)d_in[8];
    float* out = (float*)d_out;

    qtb_k1<<<BB / 8, 256>>>(x, rxa, rya, wffn, bffn, g1, b1);
    const int gx = (SSZ + SROWS - 1) / SROWS;   // 26
    qtb_k2<<<dim3(gx, NBY), 128>>>(x, g1, b1, g2, b2, out);
}